// round 3
// baseline (speedup 1.0000x reference)
#include <cuda_runtime.h>
#include <cuda_bf16.h>

#define NN 100000
#define EE 1600000
#define DD 128
#define SCAN_T 1024

// Scratch (__device__ globals per allocation rules)
__device__ float d_g[(size_t)NN * DD];     // g = dinv[i] * (x @ Wc^T)
__device__ float d_dinv[NN];
__device__ int   d_deg[NN];
__device__ int   d_rowptr[NN + 1];
__device__ int   d_cursor[NN];
__device__ int   d_srcs[EE];
__device__ float d_Wc[DD * DD];            // Wc = W_gcn @ W_lin

typedef unsigned long long u64;

__device__ __forceinline__ void ffma2(u64& d, u64 a, u64 b) {
    asm("fma.rn.f32x2 %0, %1, %2, %0;" : "+l"(d) : "l"(a), "l"(b));
}
__device__ __forceinline__ float2 unpack2(u64 v) {
    float2 r;
    asm("mov.b64 {%0,%1}, %2;" : "=f"(r.x), "=f"(r.y) : "l"(v));
    return r;
}
__device__ __forceinline__ u64 pack2(float lo, float hi) {
    u64 r;
    asm("mov.b64 %0, {%1,%2};" : "=l"(r) : "f"(lo), "f"(hi));
    return r;
}

// ---------------------------------------------------------------------------
__global__ void zero_deg_kernel(int n) {
    int i = blockIdx.x * blockDim.x + threadIdx.x;
    if (i < n) d_deg[i] = 0;
}

__global__ void count_deg_kernel(const int* __restrict__ ei, int E) {
    int e = blockIdx.x * blockDim.x + threadIdx.x;
    if (e < E) atomicAdd(&d_deg[__ldg(&ei[E + e])], 1);
}

// Single-block scan: rowptr = exclusive_scan(deg); cursor = rowptr;
// dinv = rsqrt(deg + 1)  (+1 = self loop)
__global__ __launch_bounds__(SCAN_T) void scan_kernel(int n) {
    __shared__ int ssum[SCAN_T];
    int t = threadIdx.x;
    int chunk = (n + SCAN_T - 1) / SCAN_T;
    int lo = t * chunk;
    int hi = min(lo + chunk, n);
    int s = 0;
    for (int i = lo; i < hi; i++) s += d_deg[i];
    ssum[t] = s;
    __syncthreads();
    // Hillis-Steele inclusive scan over thread sums
    for (int off = 1; off < SCAN_T; off <<= 1) {
        int tmp = (t >= off) ? ssum[t - off] : 0;
        __syncthreads();
        ssum[t] += tmp;
        __syncthreads();
    }
    int run = ssum[t] - s;  // exclusive prefix for this chunk
    for (int i = lo; i < hi; i++) {
        int d = d_deg[i];
        d_rowptr[i] = run;
        d_cursor[i] = run;
        d_dinv[i]   = rsqrtf((float)(d + 1));
        run += d;
    }
    if (t == SCAN_T - 1) d_rowptr[n] = ssum[SCAN_T - 1];
}

__global__ void fill_csr_kernel(const int* __restrict__ ei, int E) {
    int e = blockIdx.x * blockDim.x + threadIdx.x;
    if (e < E) {
        int r = __ldg(&ei[e]);
        int c = __ldg(&ei[E + e]);
        int pos = atomicAdd(&d_cursor[c], 1);
        d_srcs[pos] = r;
    }
}

// Wc[i][j] = sum_k Wg[i][k] * Wl[k][j]
__global__ void combine_w_kernel(const float* __restrict__ Wl,
                                 const float* __restrict__ Wg) {
    int i = blockIdx.x;
    int j = threadIdx.x;
    float s0 = 0.f, s1 = 0.f, s2 = 0.f, s3 = 0.f;
#pragma unroll 8
    for (int k = 0; k < DD; k += 4) {
        s0 += __ldg(&Wg[i * DD + k + 0]) * __ldg(&Wl[(k + 0) * DD + j]);
        s1 += __ldg(&Wg[i * DD + k + 1]) * __ldg(&Wl[(k + 1) * DD + j]);
        s2 += __ldg(&Wg[i * DD + k + 2]) * __ldg(&Wl[(k + 2) * DD + j]);
        s3 += __ldg(&Wg[i * DD + k + 3]) * __ldg(&Wl[(k + 3) * DD + j]);
    }
    d_Wc[i * DD + j] = (s0 + s1) + (s2 + s3);
}

// g[i][:] = dinv[i] * (x[i] @ Wc^T), packed f32x2 math.
// 64 rows x 128 cols per block, 256 threads.
__global__ __launch_bounds__(256, 2) void gemm_g_kernel(const float* __restrict__ x, int n) {
    __shared__ float2 xs[64][32];  // duplicated pairs (v,v): LDS.64 = packed multiplicand
    __shared__ float  ws[32][128]; // ws[k][c]

    const int tid = threadIdx.x;
    const int row0 = blockIdx.x * 64;
    const int tx = tid & 31;
    const int ty = tid >> 5;

    u64 acc01[8], acc23[8];
#pragma unroll
    for (int i = 0; i < 8; i++) { acc01[i] = 0ull; acc23[i] = 0ull; }

    const float4* x4 = (const float4*)x;
    const float4* w4 = (const float4*)d_Wc;

    for (int kb = 0; kb < 4; kb++) {
        // x tile: 64 rows x 8 float4, stored duplicated
#pragma unroll
        for (int rr = 0; rr < 2; rr++) {
            int r = (tid >> 3) + rr * 32;
            int f = tid & 7;
            int grow = row0 + r;
            float4 v = make_float4(0.f, 0.f, 0.f, 0.f);
            if (grow < n) v = __ldg(&x4[(long long)grow * 32 + kb * 8 + f]);
            xs[r][f * 4 + 0] = make_float2(v.x, v.x);
            xs[r][f * 4 + 1] = make_float2(v.y, v.y);
            xs[r][f * 4 + 2] = make_float2(v.z, v.z);
            xs[r][f * 4 + 3] = make_float2(v.w, v.w);
        }
        // W chunk transposed: ws[k][c]
        {
            int c = tid >> 1;
            int hb = (tid & 1) * 4;
#pragma unroll
            for (int m = 0; m < 4; m++) {
                float4 v = __ldg(&w4[c * 32 + kb * 8 + hb + m]);
                int kl = (hb + m) * 4;
                ws[kl + 0][c] = v.x;
                ws[kl + 1][c] = v.y;
                ws[kl + 2][c] = v.z;
                ws[kl + 3][c] = v.w;
            }
        }
        __syncthreads();

#pragma unroll 8
        for (int k = 0; k < 32; k++) {
            float4 w = *(const float4*)&ws[k][tx * 4];
            u64 w01 = pack2(w.x, w.y);
            u64 w23 = pack2(w.z, w.w);
#pragma unroll
            for (int i = 0; i < 8; i++) {
                u64 xv = *(const u64*)&xs[ty * 8 + i][k];
                ffma2(acc01[i], xv, w01);
                ffma2(acc23[i], xv, w23);
            }
        }
        __syncthreads();
    }

    float4* g4 = (float4*)d_g;
#pragma unroll
    for (int i = 0; i < 8; i++) {
        int r = row0 + ty * 8 + i;
        if (r < n) {
            float di = d_dinv[r];
            float2 c01 = unpack2(acc01[i]);
            float2 c23 = unpack2(acc23[i]);
            float4 o;
            o.x = c01.x * di;
            o.y = c01.y * di;
            o.z = c23.x * di;
            o.w = c23.y * di;
            g4[(long long)r * 32 + tx] = o;
        }
    }
}

// Pull-mode aggregation: one warp per node; no fp atomics.
// out[c] = dinv[c] * (g[c] + sum_{r in N_in(c)} g[r]) + b
__global__ __launch_bounds__(256) void gather_kernel(const float* __restrict__ b,
                                                     float* __restrict__ out, int n) {
    int warp = (blockIdx.x * blockDim.x + threadIdx.x) >> 5;
    if (warp >= n) return;
    int lane = threadIdx.x & 31;
    const float4* g4 = (const float4*)d_g;

    float4 a0 = g4[(long long)warp * 32 + lane];   // self loop
    float4 a1 = make_float4(0.f, 0.f, 0.f, 0.f);
    float4 a2 = a1, a3 = a1;

    int e   = __ldg(&d_rowptr[warp]);
    int end = __ldg(&d_rowptr[warp + 1]);

    for (; e + 4 <= end; e += 4) {
        int s0 = __ldg(&d_srcs[e + 0]);
        int s1 = __ldg(&d_srcs[e + 1]);
        int s2 = __ldg(&d_srcs[e + 2]);
        int s3 = __ldg(&d_srcs[e + 3]);
        float4 v0 = __ldg(&g4[(long long)s0 * 32 + lane]);
        float4 v1 = __ldg(&g4[(long long)s1 * 32 + lane]);
        float4 v2 = __ldg(&g4[(long long)s2 * 32 + lane]);
        float4 v3 = __ldg(&g4[(long long)s3 * 32 + lane]);
        a0.x += v0.x; a0.y += v0.y; a0.z += v0.z; a0.w += v0.w;
        a1.x += v1.x; a1.y += v1.y; a1.z += v1.z; a1.w += v1.w;
        a2.x += v2.x; a2.y += v2.y; a2.z += v2.z; a2.w += v2.w;
        a3.x += v3.x; a3.y += v3.y; a3.z += v3.z; a3.w += v3.w;
    }
    for (; e < end; e++) {
        int s = __ldg(&d_srcs[e]);
        float4 v = __ldg(&g4[(long long)s * 32 + lane]);
        a0.x += v.x; a0.y += v.y; a0.z += v.z; a0.w += v.w;
    }

    float di = d_dinv[warp];
    float4 bb = __ldg(&((const float4*)b)[lane]);
    float4 o;
    o.x = di * (a0.x + a1.x + a2.x + a3.x) + bb.x;
    o.y = di * (a0.y + a1.y + a2.y + a3.y) + bb.y;
    o.z = di * (a0.z + a1.z + a2.z + a3.z) + bb.z;
    o.w = di * (a0.w + a1.w + a2.w + a3.w) + bb.w;
    ((float4*)out)[(long long)warp * 32 + lane] = o;
}

extern "C" void kernel_launch(void* const* d_in, const int* in_sizes, int n_in,
                              void* d_out, int out_size) {
    const float* x  = (const float*)d_in[0];
    const int*   ei = (const int*)d_in[1];     // int32 on device
    const float* Wl = (const float*)d_in[2];
    const float* Wg = (const float*)d_in[3];
    const float* b  = (const float*)d_in[4];
    float* out = (float*)d_out;

    int n = in_sizes[0] / DD;     // 100000
    int E = in_sizes[1] / 2;      // 1600000

    zero_deg_kernel<<<(n + 255) / 256, 256>>>(n);
    count_deg_kernel<<<(E + 255) / 256, 256>>>(ei, E);
    scan_kernel<<<1, SCAN_T>>>(n);
    fill_csr_kernel<<<(E + 255) / 256, 256>>>(ei, E);
    combine_w_kernel<<<DD, DD>>>(Wl, Wg);
    gemm_g_kernel<<<(n + 63) / 64, 256>>>(x, n);

    int gblocks = (n * 32 + 255) / 256;   // one warp per node
    gather_kernel<<<gblocks, 256>>>(b, out, n);
}

// round 4
// speedup vs baseline: 1.0344x; 1.0344x over previous
#include <cuda_runtime.h>
#include <cuda_bf16.h>

#define NN 100000
#define EE 1600000
#define DD 128
#define SCAN_T 1024

// Scratch (__device__ globals per allocation rules)
__device__ float d_g[(size_t)NN * DD];     // g = dinv[i] * (x @ Wc^T)
__device__ float d_dinv[NN];
__device__ int   d_deg[NN];
__device__ int   d_rowptr[NN + 1];
__device__ int   d_cursor[NN];
__device__ int   d_srcs[EE];
__device__ float d_Wc[DD * DD];            // Wc = W_gcn @ W_lin

// ---------------------------------------------------------------------------
__global__ void zero_deg_kernel(int n) {
    int i = blockIdx.x * blockDim.x + threadIdx.x;
    if (i < n) d_deg[i] = 0;
}

// count in-degrees; 4 edges per thread (int4 load of targets)
__global__ void count_deg_kernel(const int* __restrict__ ei, int E) {
    int t = blockIdx.x * blockDim.x + threadIdx.x;
    int e = t * 4;
    if (e + 4 <= E) {
        int4 c = __ldg((const int4*)&ei[E + e]);
        atomicAdd(&d_deg[c.x], 1);
        atomicAdd(&d_deg[c.y], 1);
        atomicAdd(&d_deg[c.z], 1);
        atomicAdd(&d_deg[c.w], 1);
    } else {
        for (; e < E; e++) atomicAdd(&d_deg[__ldg(&ei[E + e])], 1);
    }
}

// Single-block scan: rowptr = exclusive_scan(deg); cursor = rowptr;
// dinv = rsqrt(deg + 1)  (+1 = self loop)
__global__ __launch_bounds__(SCAN_T) void scan_kernel(int n) {
    __shared__ int ssum[SCAN_T];
    int t = threadIdx.x;
    int chunk = (n + SCAN_T - 1) / SCAN_T;
    int lo = t * chunk;
    int hi = min(lo + chunk, n);
    int s = 0;
    for (int i = lo; i < hi; i++) s += d_deg[i];
    ssum[t] = s;
    __syncthreads();
    for (int off = 1; off < SCAN_T; off <<= 1) {
        int tmp = (t >= off) ? ssum[t - off] : 0;
        __syncthreads();
        ssum[t] += tmp;
        __syncthreads();
    }
    int run = ssum[t] - s;
    for (int i = lo; i < hi; i++) {
        int d = d_deg[i];
        d_rowptr[i] = run;
        d_cursor[i] = run;
        d_dinv[i]   = rsqrtf((float)(d + 1));
        run += d;
    }
    if (t == SCAN_T - 1) d_rowptr[n] = ssum[SCAN_T - 1];
}

// CSR fill; 4 edges per thread
__global__ void fill_csr_kernel(const int* __restrict__ ei, int E) {
    int t = blockIdx.x * blockDim.x + threadIdx.x;
    int e = t * 4;
    if (e + 4 <= E) {
        int4 r = __ldg((const int4*)&ei[e]);
        int4 c = __ldg((const int4*)&ei[E + e]);
        d_srcs[atomicAdd(&d_cursor[c.x], 1)] = r.x;
        d_srcs[atomicAdd(&d_cursor[c.y], 1)] = r.y;
        d_srcs[atomicAdd(&d_cursor[c.z], 1)] = r.z;
        d_srcs[atomicAdd(&d_cursor[c.w], 1)] = r.w;
    } else {
        for (; e < E; e++) {
            int r = __ldg(&ei[e]);
            int c = __ldg(&ei[E + e]);
            d_srcs[atomicAdd(&d_cursor[c], 1)] = r;
        }
    }
}

// Wc[i][j] = sum_k Wg[i][k] * Wl[k][j]
__global__ void combine_w_kernel(const float* __restrict__ Wl,
                                 const float* __restrict__ Wg) {
    int i = blockIdx.x;
    int j = threadIdx.x;
    float s0 = 0.f, s1 = 0.f, s2 = 0.f, s3 = 0.f;
#pragma unroll 8
    for (int k = 0; k < DD; k += 4) {
        s0 += __ldg(&Wg[i * DD + k + 0]) * __ldg(&Wl[(k + 0) * DD + j]);
        s1 += __ldg(&Wg[i * DD + k + 1]) * __ldg(&Wl[(k + 1) * DD + j]);
        s2 += __ldg(&Wg[i * DD + k + 2]) * __ldg(&Wl[(k + 2) * DD + j]);
        s3 += __ldg(&Wg[i * DD + k + 3]) * __ldg(&Wl[(k + 3) * DD + j]);
    }
    d_Wc[i * DD + j] = (s0 + s1) + (s2 + s3);
}

// g[i][:] = dinv[i] * (x[i] @ Wc^T)  — R2-proven plain-FFMA version.
__global__ __launch_bounds__(256, 2) void gemm_g_kernel(const float* __restrict__ x, int n) {
    __shared__ float xs[64][32];
    __shared__ float ws[32][128];

    const int tid = threadIdx.x;
    const int row0 = blockIdx.x * 64;
    const int tx = tid & 31;
    const int ty = tid >> 5;

    float4 acc[8];
#pragma unroll
    for (int i = 0; i < 8; i++) acc[i] = make_float4(0.f, 0.f, 0.f, 0.f);

    const float4* x4 = (const float4*)x;
    const float4* w4 = (const float4*)d_Wc;

    for (int kb = 0; kb < 4; kb++) {
#pragma unroll
        for (int rr = 0; rr < 2; rr++) {
            int r = (tid >> 3) + rr * 32;
            int f = tid & 7;
            int grow = row0 + r;
            float4 v = make_float4(0.f, 0.f, 0.f, 0.f);
            if (grow < n) v = __ldg(&x4[(long long)grow * 32 + kb * 8 + f]);
            *(float4*)&xs[r][f * 4] = v;
        }
        {
            int c = tid >> 1;
            int hb = (tid & 1) * 4;
#pragma unroll
            for (int m = 0; m < 4; m++) {
                float4 v = __ldg(&w4[c * 32 + kb * 8 + hb + m]);
                int kl = (hb + m) * 4;
                ws[kl + 0][c] = v.x;
                ws[kl + 1][c] = v.y;
                ws[kl + 2][c] = v.z;
                ws[kl + 3][c] = v.w;
            }
        }
        __syncthreads();

#pragma unroll 8
        for (int k = 0; k < 32; k++) {
            float4 w = *(const float4*)&ws[k][tx * 4];
#pragma unroll
            for (int i = 0; i < 8; i++) {
                float xv = xs[ty * 8 + i][k];
                acc[i].x += xv * w.x;
                acc[i].y += xv * w.y;
                acc[i].z += xv * w.z;
                acc[i].w += xv * w.w;
            }
        }
        __syncthreads();
    }

    float4* g4 = (float4*)d_g;
#pragma unroll
    for (int i = 0; i < 8; i++) {
        int r = row0 + ty * 8 + i;
        if (r < n) {
            float di = d_dinv[r];
            float4 o;
            o.x = acc[i].x * di;
            o.y = acc[i].y * di;
            o.z = acc[i].z * di;
            o.w = acc[i].w * di;
            g4[(long long)r * 32 + tx] = o;
        }
    }
}

// Pull aggregation: one warp per node. Coalesced per-lane index preload +
// shfl broadcast -> up to 32 independent row gathers in flight per warp.
__global__ __launch_bounds__(256) void gather_kernel(const float* __restrict__ b,
                                                     float* __restrict__ out, int n) {
    int node = (blockIdx.x * blockDim.x + threadIdx.x) >> 5;
    if (node >= n) return;
    int lane = threadIdx.x & 31;
    const float4* g4 = (const float4*)d_g;

    float4 a0 = g4[(long long)node * 32 + lane];   // self loop
    float4 a1 = make_float4(0.f, 0.f, 0.f, 0.f);

    int start = __ldg(&d_rowptr[node]);
    int end   = __ldg(&d_rowptr[node + 1]);

    for (int base = start; base < end; base += 32) {
        int cnt = min(32, end - base);
        int s = 0;
        if (base + lane < end) s = __ldg(&d_srcs[base + lane]);
        int j = 0;
#pragma unroll 2
        for (; j + 2 <= cnt; j += 2) {
            int s0 = __shfl_sync(0xffffffffu, s, j);
            int s1 = __shfl_sync(0xffffffffu, s, j + 1);
            float4 v0 = __ldg(&g4[(long long)s0 * 32 + lane]);
            float4 v1 = __ldg(&g4[(long long)s1 * 32 + lane]);
            a0.x += v0.x; a0.y += v0.y; a0.z += v0.z; a0.w += v0.w;
            a1.x += v1.x; a1.y += v1.y; a1.z += v1.z; a1.w += v1.w;
        }
        if (j < cnt) {
            int s0 = __shfl_sync(0xffffffffu, s, j);
            float4 v0 = __ldg(&g4[(long long)s0 * 32 + lane]);
            a0.x += v0.x; a0.y += v0.y; a0.z += v0.z; a0.w += v0.w;
        }
    }

    float di = d_dinv[node];
    float4 bb = __ldg(&((const float4*)b)[lane]);
    float4 o;
    o.x = di * (a0.x + a1.x) + bb.x;
    o.y = di * (a0.y + a1.y) + bb.y;
    o.z = di * (a0.z + a1.z) + bb.z;
    o.w = di * (a0.w + a1.w) + bb.w;
    ((float4*)out)[(long long)node * 32 + lane] = o;
}

extern "C" void kernel_launch(void* const* d_in, const int* in_sizes, int n_in,
                              void* d_out, int out_size) {
    const float* x  = (const float*)d_in[0];
    const int*   ei = (const int*)d_in[1];     // int32 on device
    const float* Wl = (const float*)d_in[2];
    const float* Wg = (const float*)d_in[3];
    const float* b  = (const float*)d_in[4];
    float* out = (float*)d_out;

    int n = in_sizes[0] / DD;     // 100000
    int E = in_sizes[1] / 2;      // 1600000

    zero_deg_kernel<<<(n + 255) / 256, 256>>>(n);
    int qthreads = (E + 3) / 4;
    count_deg_kernel<<<(qthreads + 255) / 256, 256>>>(ei, E);
    scan_kernel<<<1, SCAN_T>>>(n);
    fill_csr_kernel<<<(qthreads + 255) / 256, 256>>>(ei, E);
    combine_w_kernel<<<DD, DD>>>(Wl, Wg);
    gemm_g_kernel<<<(n + 63) / 64, 256>>>(x, n);

    int gblocks = (n * 32 + 255) / 256;   // one warp per node
    gather_kernel<<<gblocks, 256>>>(b, out, n);
}

// round 5
// speedup vs baseline: 1.5633x; 1.5113x over previous
#include <cuda_runtime.h>
#include <cuda_bf16.h>
#include <mma.h>

using namespace nvcuda;

#define NN 100000
#define EE 1600000
#define DD 128

// Scratch (__device__ globals per allocation rules). d_g padded by 64 rows so
// the last GEMM block's full-tile wmma stores stay in-bounds.
__device__ float d_g[(size_t)(NN + 64) * DD];
__device__ float d_dinv[NN];
__device__ int   d_deg[NN];
__device__ float d_WcT[DD * DD];   // WcT[k][c] = Wc[c][k], tf32-rounded

// ---------------------------------------------------------------------------
// 1) deg init (self loop => 1)
__global__ void init_deg_kernel(int n) {
    int i = blockIdx.x * blockDim.x + threadIdx.x;
    if (i < n) d_deg[i] = 1;
}

// 2) zero d_out (poisoned by harness)
__global__ void zero_out_kernel(float4* __restrict__ out4, int n4) {
    int i = blockIdx.x * blockDim.x + threadIdx.x;
    if (i < n4) out4[i] = make_float4(0.f, 0.f, 0.f, 0.f);
}

// 3) count in-degrees over edge targets; 4 edges per thread (E % 4 == 0)
__global__ void count_deg_kernel(const int* __restrict__ ei, int E) {
    int t = blockIdx.x * blockDim.x + threadIdx.x;
    int e = t * 4;
    if (e + 4 <= E) {
        int4 c = __ldg((const int4*)&ei[E + e]);
        atomicAdd(&d_deg[c.x], 1);
        atomicAdd(&d_deg[c.y], 1);
        atomicAdd(&d_deg[c.z], 1);
        atomicAdd(&d_deg[c.w], 1);
    } else {
        for (; e < E; e++) atomicAdd(&d_deg[__ldg(&ei[E + e])], 1);
    }
}

// 4) dinv = rsqrt(deg)
__global__ void dinv_kernel(int n) {
    int i = blockIdx.x * blockDim.x + threadIdx.x;
    if (i < n) d_dinv[i] = rsqrtf((float)d_deg[i]);
}

// 5) WcT[k][c] = Wc[c][k] = sum_m Wg[c][m] * Wl[m][k], rounded to tf32
__global__ void combine_w_kernel(const float* __restrict__ Wl,
                                 const float* __restrict__ Wg) {
    int k = blockIdx.x;   // 128 blocks = output row of WcT
    int c = threadIdx.x;  // 128 threads = output col
    float s0 = 0.f, s1 = 0.f, s2 = 0.f, s3 = 0.f;
#pragma unroll 8
    for (int m = 0; m < DD; m += 4) {
        s0 += __ldg(&Wg[c * DD + m + 0]) * __ldg(&Wl[(m + 0) * DD + k]);
        s1 += __ldg(&Wg[c * DD + m + 1]) * __ldg(&Wl[(m + 1) * DD + k]);
        s2 += __ldg(&Wg[c * DD + m + 2]) * __ldg(&Wl[(m + 2) * DD + k]);
        s3 += __ldg(&Wg[c * DD + m + 3]) * __ldg(&Wl[(m + 3) * DD + k]);
    }
    d_WcT[k * DD + c] = wmma::__float_to_tf32((s0 + s1) + (s2 + s3));
}

// 6) g[i][:] = (dinv[i] * x[i]) @ WcT   — tf32 tensor-core GEMM.
//    Block: 64 rows x 128 cols, 256 threads = 8 warps.
//    Warp w: rows 16*(w>>1), cols 64*(w&1) -> 4 acc fragments of 16x16.
__global__ __launch_bounds__(256, 2) void gemm_g_kernel(const float* __restrict__ x, int n) {
    __shared__ float xs[64][36];    // padded ld=36: rotates banks for ldmatrix
    __shared__ float ws[32][132];   // padded ld=132

    const int tid = threadIdx.x;
    const int row0 = blockIdx.x * 64;
    const int warp = tid >> 5;
    const int row_w = (warp >> 1) * 16;
    const int col_w = (warp & 1) * 64;

    wmma::fragment<wmma::accumulator, 16, 16, 8, float> acc[4];
#pragma unroll
    for (int j = 0; j < 4; j++) wmma::fill_fragment(acc[j], 0.0f);

    const float4* x4 = (const float4*)x;
    const float4* w4 = (const float4*)d_WcT;

    for (int kb = 0; kb < 4; kb++) {
        // x tile: 64 rows x 32 cols of this K-chunk, scaled by dinv, tf32-rounded
#pragma unroll
        for (int rr = 0; rr < 2; rr++) {
            int r = (tid >> 3) + rr * 32;
            int f = tid & 7;                   // float4 index within the 8-chunk
            int grow = row0 + r;
            float4 v = make_float4(0.f, 0.f, 0.f, 0.f);
            float di = 0.f;
            if (grow < n) {
                v = __ldg(&x4[(long long)grow * 32 + kb * 8 + f]);
                di = d_dinv[grow];
            }
            float4 o;
            o.x = wmma::__float_to_tf32(v.x * di);
            o.y = wmma::__float_to_tf32(v.y * di);
            o.z = wmma::__float_to_tf32(v.z * di);
            o.w = wmma::__float_to_tf32(v.w * di);
            *(float4*)&xs[r][f * 4] = o;       // 16B-aligned (144*r + 16*f)
        }
        // WcT chunk: rows kb*32..+31, 128 cols (already tf32-rounded)
        {
#pragma unroll
            for (int q = 0; q < 4; q++) {
                int lin = tid * 4 + q;          // 0..1023 float4s
                int kl = lin >> 5;              // 32 float4 per row
                int fc = lin & 31;
                float4 v = __ldg(&w4[(kb * 32 + kl) * 32 + fc]);
                *(float4*)&ws[kl][fc * 4] = v;  // 16B-aligned (528*kl + 16*fc)
            }
        }
        __syncthreads();

#pragma unroll
        for (int ks = 0; ks < 4; ks++) {
            wmma::fragment<wmma::matrix_a, 16, 16, 8, wmma::precision::tf32, wmma::row_major> a;
            wmma::load_matrix_sync(a, &xs[row_w][ks * 8], 36);
#pragma unroll
            for (int j = 0; j < 4; j++) {
                wmma::fragment<wmma::matrix_b, 16, 16, 8, wmma::precision::tf32, wmma::row_major> b;
                wmma::load_matrix_sync(b, &ws[ks * 8][col_w + j * 16], 132);
                wmma::mma_sync(acc[j], a, b, acc[j]);
            }
        }
        __syncthreads();
    }

#pragma unroll
    for (int j = 0; j < 4; j++) {
        wmma::store_matrix_sync(&d_g[(long long)(row0 + row_w) * DD + col_w + j * 16],
                                acc[j], DD, wmma::mem_row_major);
    }
}

// 7) scatter: one warp per edge group (EPW edges), vectorized v4 reductions
#define EPW 4
__global__ void scatter_kernel(const int* __restrict__ ei,
                               float* __restrict__ out, int E) {
    int warp = (blockIdx.x * blockDim.x + threadIdx.x) >> 5;
    int lane = threadIdx.x & 31;
    const float4* g4 = (const float4*)d_g;
    long long base = (long long)warp * EPW;
#pragma unroll
    for (int t = 0; t < EPW; t++) {
        long long e = base + t;
        if (e >= E) return;
        int r = __ldg(&ei[e]);
        int c = __ldg(&ei[E + e]);
        float4 v = __ldg(&g4[(long long)r * 32 + lane]);
        float* addr = out + (long long)c * DD + lane * 4;
        asm volatile("red.global.add.v4.f32 [%0], {%1,%2,%3,%4};"
                     :: "l"(addr), "f"(v.x), "f"(v.y), "f"(v.z), "f"(v.w)
                     : "memory");
    }
}

// 8) finalize: out[i][:] = dinv[i] * (acc + g[i]) + b
__global__ void finalize_kernel(const float* __restrict__ b,
                                float* __restrict__ out, int n4total) {
    int idx = blockIdx.x * blockDim.x + threadIdx.x;
    if (idx >= n4total) return;
    int i = idx >> 5;
    int q = idx & 31;
    float di = d_dinv[i];
    float4 a = ((float4*)out)[idx];
    float4 g = ((const float4*)d_g)[idx];
    float4 bb = __ldg(&((const float4*)b)[q]);
    float4 o;
    o.x = di * (a.x + g.x) + bb.x;
    o.y = di * (a.y + g.y) + bb.y;
    o.z = di * (a.z + g.z) + bb.z;
    o.w = di * (a.w + g.w) + bb.w;
    ((float4*)out)[idx] = o;
}

extern "C" void kernel_launch(void* const* d_in, const int* in_sizes, int n_in,
                              void* d_out, int out_size) {
    const float* x  = (const float*)d_in[0];
    const int*   ei = (const int*)d_in[1];     // int32 on device
    const float* Wl = (const float*)d_in[2];
    const float* Wg = (const float*)d_in[3];
    const float* b  = (const float*)d_in[4];
    float* out = (float*)d_out;

    int n = in_sizes[0] / DD;     // 100000
    int E = in_sizes[1] / 2;      // 1600000
    int n4 = n * (DD / 4);

    init_deg_kernel<<<(n + 255) / 256, 256>>>(n);
    zero_out_kernel<<<(n4 + 255) / 256, 256>>>((float4*)out, n4);
    int qthreads = (E + 3) / 4;
    count_deg_kernel<<<(qthreads + 255) / 256, 256>>>(ei, E);
    dinv_kernel<<<(n + 255) / 256, 256>>>(n);
    combine_w_kernel<<<DD, DD>>>(Wl, Wg);
    gemm_g_kernel<<<(n + 63) / 64, 256>>>(x, n);

    int warps = (E + EPW - 1) / EPW;
    int sblocks = (warps * 32 + 255) / 256;
    scatter_kernel<<<sblocks, 256>>>(ei, out, E);

    finalize_kernel<<<(n4 + 255) / 256, 256>>>(b, out, n4);
}